// round 9
// baseline (speedup 1.0000x reference)
#include <cuda_runtime.h>
#include <cuda_bf16.h>

#define HDIM 1024
#define VDIM 50257
#define SDIM 4096
#define NBA 32                 // attention group blocks (sub-grid barrier)
#define NCH 32                 // S-chunks for context partials
#define SCH (SDIM / NCH)       // 128
#define NBF 148                // k_fin persistent blocks
#define NTF 1024

// ---------------- scratch (no allocations allowed) ----------------
__device__ float g_hnew[HDIM];
__device__ float g_context[HDIM];
__device__ float g_scores[SDIM];        // scores, then normalized attn in place
__device__ float g_cpart[NCH * HDIM];
__device__ float g_lse[1];
__device__ float2 g_pair[NBF];
__device__ unsigned g_barA_count = 0;   // k_mid group-A barrier
__device__ unsigned g_barA_gen = 0;
__device__ unsigned g_barF_count = 0;   // k_fin barrier
__device__ unsigned g_barF_gen = 0;

// ---------------- helpers ----------------
__device__ __forceinline__ float warpSum(float v) {
#pragma unroll
    for (int o = 16; o > 0; o >>= 1) v += __shfl_xor_sync(0xffffffffu, v, o);
    return v;
}
__device__ __forceinline__ float warpMax(float v) {
#pragma unroll
    for (int o = 16; o > 0; o >>= 1) v = fmaxf(v, __shfl_xor_sync(0xffffffffu, v, o));
    return v;
}
__device__ __forceinline__ float dot4(float4 a, float4 b) {
    return a.x * b.x + a.y * b.y + a.z * b.z + a.w * b.w;
}
__device__ __forceinline__ void subBarrier(unsigned* cnt, unsigned* gen, unsigned n) {
    __threadfence();
    __syncthreads();
    if (threadIdx.x == 0) {
        unsigned g = *((volatile unsigned*)gen);
        if (atomicAdd(cnt, 1u) == n - 1) {
            *cnt = 0;
            __threadfence();
            atomicExch(gen, g + 1);
        } else {
            while (*((volatile unsigned*)gen) == g) { __nanosleep(32); }
        }
    }
    __syncthreads();
    __threadfence();
}

// ================= kernel 1: GRU cell (R5 version, proven) =================
__global__ __launch_bounds__(256) void k_gru(
    const int* __restrict__ word_input,
    const float* __restrict__ last_context,
    const float* __restrict__ last_hidden,
    const float* __restrict__ embedding,
    const float* __restrict__ w_ih,
    const float* __restrict__ w_hh,
    const float* __restrict__ b_ih,
    const float* __restrict__ b_hh,
    float* __restrict__ hnew_out)
{
    __shared__ float sx[2 * HDIM];
    __shared__ float sh[HDIM];
    __shared__ float rbuf[6][8];

    const int j = blockIdx.x;
    const int t = threadIdx.x;
    const int word = word_input[0];
    const float* erow = embedding + (size_t)word * HDIM;

    for (int k = t; k < HDIM; k += 256) {
        sx[k]        = erow[k];
        sx[HDIM + k] = last_context[k];
        sh[k]        = last_hidden[k];
    }
    __syncthreads();

    const float4* x4 = (const float4*)sx;
    const float4* h4 = (const float4*)sh;
    const float4* wr = (const float4*)(w_ih + (size_t)j * (2 * HDIM));
    const float4* wz = (const float4*)(w_ih + (size_t)(j + HDIM) * (2 * HDIM));
    const float4* wn = (const float4*)(w_ih + (size_t)(j + 2 * HDIM) * (2 * HDIM));
    const float4* ur = (const float4*)(w_hh + (size_t)j * HDIM);
    const float4* uz = (const float4*)(w_hh + (size_t)(j + HDIM) * HDIM);
    const float4* un = (const float4*)(w_hh + (size_t)(j + 2 * HDIM) * HDIM);

    float a0 = 0.f, a1 = 0.f, a2 = 0.f, c0 = 0.f, c1 = 0.f, c2 = 0.f;
#pragma unroll
    for (int i = t; i < 512; i += 256) {
        float4 xv = x4[i];
        a0 += dot4(__ldcs(&wr[i]), xv);
        a1 += dot4(__ldcs(&wz[i]), xv);
        a2 += dot4(__ldcs(&wn[i]), xv);
    }
    {
        int i = t;
        float4 hv = h4[i];
        c0 += dot4(__ldcs(&ur[i]), hv);
        c1 += dot4(__ldcs(&uz[i]), hv);
        c2 += dot4(__ldcs(&un[i]), hv);
    }

    a0 = warpSum(a0); a1 = warpSum(a1); a2 = warpSum(a2);
    c0 = warpSum(c0); c1 = warpSum(c1); c2 = warpSum(c2);
    const int lane = t & 31, w = t >> 5;
    if (lane == 0) {
        rbuf[0][w] = a0; rbuf[1][w] = a1; rbuf[2][w] = a2;
        rbuf[3][w] = c0; rbuf[4][w] = c1; rbuf[5][w] = c2;
    }
    __syncthreads();
    if (t == 0) {
        float s[6];
#pragma unroll
        for (int q = 0; q < 6; q++) {
            float acc = 0.f;
#pragma unroll
            for (int p = 0; p < 8; p++) acc += rbuf[q][p];
            s[q] = acc;
        }
        float gir = s[0] + b_ih[j];
        float giz = s[1] + b_ih[j + HDIM];
        float gin = s[2] + b_ih[j + 2 * HDIM];
        float ghr = s[3] + b_hh[j];
        float ghz = s[4] + b_hh[j + HDIM];
        float ghn = s[5] + b_hh[j + 2 * HDIM];
        float r = 1.f / (1.f + expf(-(gir + ghr)));
        float z = 1.f / (1.f + expf(-(giz + ghz)));
        float n = tanhf(gin + r * ghn);
        float hn = (1.f - z) * n + z * sh[j];
        g_hnew[j] = hn;
        hnew_out[j] = hn;
    }
}

// ================= kernel 2: attention chain || h-half of logits =================
// blocks [0, NBA): scores -> softmax -> context (sub-grid barrier over NBA blocks)
// blocks [NBA, ...): logits_h[r] = out_w[r, 0:H] @ h_new + out_b[r]  (206 MB stream)
__global__ __launch_bounds__(256) void k_mid(
    const float* __restrict__ enc,
    const float* __restrict__ out_w,
    const float* __restrict__ out_b,
    float* __restrict__ logits,
    float* __restrict__ attn_out,
    float* __restrict__ ctx_out)
{
    __shared__ float sbuf[HDIM];     // group A: h_new; group B: y_h
    __shared__ float sa[SCH];        // group A: attn chunk
    __shared__ float rb[8];

    const int b = blockIdx.x;
    const int t = threadIdx.x;
    const int lane = t & 31, wp = t >> 5;

    if (b >= NBA) {
        // ---------------- group B: h-half logits ----------------
        for (int k = t; k < HDIM; k += 256) sbuf[k] = g_hnew[k];
        __syncthreads();
        const int r = (b - NBA) * 8 + wp;
        if (r >= VDIM) return;
        const float4* w4 = (const float4*)(out_w + (size_t)r * (2 * HDIM)); // first half
        const float4* y4 = (const float4*)sbuf;
        float acc = 0.f;
#pragma unroll
        for (int i = lane; i < 256; i += 32)
            acc += dot4(__ldcs(&w4[i]), y4[i]);
        acc = warpSum(acc);
        if (lane == 0) logits[r] = acc + out_b[r];
        return;
    }

    // ---------------- group A: attention chain ----------------
    // Phase 1: scores (warp per s row; NBA*8 = 256 warps, 16 rows each)
    for (int k = t; k < HDIM; k += 256) sbuf[k] = g_hnew[k];
    __syncthreads();
    {
        const float4* h4 = (const float4*)sbuf;
        for (int s = b * 8 + wp; s < SDIM; s += NBA * 8) {
            const float4* e4 = (const float4*)(enc + (size_t)s * HDIM);
            float acc = 0.f;
#pragma unroll
            for (int i = 0; i < 8; i++) {
                int idx = lane + 32 * i;
                acc += dot4(e4[idx], h4[idx]);
            }
            acc = warpSum(acc);
            if (lane == 0) g_scores[s] = acc;
        }
    }
    subBarrier(&g_barA_count, &g_barA_gen, NBA);

    // Phase 2: softmax over S (block 0 only), in-place normalize
    if (b == 0) {
        float v[16];
#pragma unroll
        for (int i = 0; i < 16; i++) v[i] = g_scores[t + 256 * i];
        float m = v[0];
#pragma unroll
        for (int i = 1; i < 16; i++) m = fmaxf(m, v[i]);
        m = warpMax(m);
        if (lane == 0) rb[wp] = m;
        __syncthreads();
        float M = fmaxf(fmaxf(rb[0], rb[1]), fmaxf(rb[2], rb[3]));
        M = fmaxf(M, fmaxf(fmaxf(rb[4], rb[5]), fmaxf(rb[6], rb[7])));
        float s = 0.f;
#pragma unroll
        for (int i = 0; i < 16; i++) { v[i] = expf(v[i] - M); s += v[i]; }
        s = warpSum(s);
        __syncthreads();
        if (lane == 0) rb[wp] = s;
        __syncthreads();
        float S = rb[0] + rb[1] + rb[2] + rb[3] + rb[4] + rb[5] + rb[6] + rb[7];
        const float inv = 1.f / S;
#pragma unroll
        for (int i = 0; i < 16; i++) {
            float a = v[i] * inv;
            g_scores[t + 256 * i] = a;
            attn_out[t + 256 * i] = a;
        }
    }
    subBarrier(&g_barA_count, &g_barA_gen, NBA);

    // Phase 3: context partials (block per S-chunk of 128 rows)
    {
        const int s0 = b * SCH;
        if (t < SCH) sa[t] = g_scores[s0 + t];
        __syncthreads();
#pragma unroll
        for (int c = 0; c < 4; c++) {
            const int k = t + 256 * c;
            const float* base = enc + (size_t)s0 * HDIM + k;
            float acc = 0.f;
#pragma unroll 8
            for (int s = 0; s < SCH; s++)
                acc += sa[s] * base[(size_t)s * HDIM];
            g_cpart[b * HDIM + k] = acc;
        }
    }
    subBarrier(&g_barA_count, &g_barA_gen, NBA);

    // Phase 4: context reduce (block 0)
    if (b == 0) {
#pragma unroll
        for (int c = 0; c < 4; c++) {
            const int k = t + 256 * c;
            float acc = 0.f;
#pragma unroll
            for (int p = 0; p < NCH; p++) acc += g_cpart[p * HDIM + k];
            g_context[k] = acc;
            ctx_out[k] = acc;
        }
    }
}

// ================= kernel 3: c-half logits + log-softmax =================
// persistent NBF x NTF; warp per row: logit = logits[r] + out_w[r, H:2H] @ context
// online (m,s) on the fly; grid barrier; combine; subtract.
__global__ __launch_bounds__(NTF, 1) void k_fin(
    const float* __restrict__ out_w,
    float* __restrict__ out)
{
    __shared__ float sy[HDIM];
    __shared__ float rm[32], rs[32];

    const int t = threadIdx.x, b = blockIdx.x;
    const int lane = t & 31, wp = t >> 5;
    const int gwarp = b * 32 + wp;          // 0..4735

    for (int k = t; k < HDIM; k += NTF) sy[k] = g_context[k];
    __syncthreads();
    const float4* y4 = (const float4*)sy;

    float m = -1e30f, s = 0.f;              // lane0-tracked online lse
    for (int r = gwarp; r < VDIM; r += NBF * 32) {
        const float4* w4 = (const float4*)(out_w + (size_t)r * (2 * HDIM) + HDIM);
        float acc = 0.f;
#pragma unroll
        for (int i = lane; i < 256; i += 32)
            acc += dot4(__ldcs(&w4[i]), y4[i]);
        acc = warpSum(acc);
        if (lane == 0) {
            float lg = out[r] + acc;        // h-half + bias already there
            out[r] = lg;
            float M = fmaxf(m, lg);
            s = s * expf(m - M) + expf(lg - M);
            m = M;
        }
    }
    if (lane == 0) { rm[wp] = m; rs[wp] = s; }
    __syncthreads();
    if (t == 0) {
        float M = rm[0], S = rs[0];
#pragma unroll
        for (int p = 1; p < 32; p++) {
            float M2 = fmaxf(M, rm[p]);
            S = S * expf(M - M2) + rs[p] * expf(rm[p] - M2);
            M = M2;
        }
        g_pair[b] = make_float2(M, S);
    }
    subBarrier(&g_barF_count, &g_barF_gen, NBF);
    if (b == 0 && t == 0) {
        float2 p0 = g_pair[0];
        float M = p0.x, S = p0.y;
        for (int p = 1; p < NBF; p++) {
            float2 pp = g_pair[p];
            float M2 = fmaxf(M, pp.x);
            S = S * expf(M - M2) + pp.y * expf(pp.x - M2);
            M = M2;
        }
        g_lse[0] = M + logf(S);
    }
    subBarrier(&g_barF_count, &g_barF_gen, NBF);
    const float lse = g_lse[0];
    for (int v = b * NTF + t; v < VDIM; v += NBF * NTF) out[v] -= lse;
}

// ---------------- launch ----------------
extern "C" void kernel_launch(void* const* d_in, const int* in_sizes, int n_in,
                              void* d_out, int out_size)
{
    const int*   word         = (const int*)d_in[0];
    const float* last_context = (const float*)d_in[1];
    const float* last_hidden  = (const float*)d_in[2];
    const float* enc          = (const float*)d_in[3];
    const float* embedding    = (const float*)d_in[4];
    const float* w_ih         = (const float*)d_in[5];
    const float* w_hh         = (const float*)d_in[6];
    const float* b_ih         = (const float*)d_in[7];
    const float* b_hh         = (const float*)d_in[8];
    const float* out_w        = (const float*)d_in[9];
    const float* out_b        = (const float*)d_in[10];

    float* out      = (float*)d_out;
    float* o_logits = out;                    // [V]   log_softmax output
    float* o_ctx    = out + VDIM;             // [H]   context
    float* o_hnew   = out + VDIM + HDIM;      // [H]   h_new
    float* o_attn   = out + VDIM + 2 * HDIM;  // [S]   attn

    k_gru<<<HDIM, 256>>>(word, last_context, last_hidden, embedding,
                         w_ih, w_hh, b_ih, b_hh, o_hnew);
    k_mid<<<NBA + (VDIM + 7) / 8, 256>>>(enc, out_w, out_b, o_logits, o_attn, o_ctx);
    k_fin<<<NBF, NTF>>>(out_w, o_logits);
}

// round 10
// speedup vs baseline: 1.2269x; 1.2269x over previous
#include <cuda_runtime.h>
#include <cuda_bf16.h>

#define HDIM 1024
#define VDIM 50257
#define SDIM 4096
#define NCHUNK 256
#define CHUNK  (SDIM / NCHUNK)   // 16
#define NBF 148
#define NTF 1024

// ---------------- scratch (no allocations allowed) ----------------
__device__ float g_hnew[HDIM];
__device__ float g_context[HDIM];
__device__ float g_scores[SDIM];
__device__ float g_gates[6 * HDIM];   // [0,3H): gi ; [3H,6H): gh
__device__ float g_cpart[NCHUNK * HDIM];
__device__ float g_lse[1];
__device__ float2 g_pair[NBF];
__device__ unsigned g_barF_count = 0;
__device__ unsigned g_barF_gen = 0;

// ---------------- helpers ----------------
__device__ __forceinline__ float warpSum(float v) {
#pragma unroll
    for (int o = 16; o > 0; o >>= 1) v += __shfl_xor_sync(0xffffffffu, v, o);
    return v;
}
__device__ __forceinline__ float warpMax(float v) {
#pragma unroll
    for (int o = 16; o > 0; o >>= 1) v = fmaxf(v, __shfl_xor_sync(0xffffffffu, v, o));
    return v;
}
__device__ __forceinline__ float dot4(float4 a, float4 b) {
    return a.x * b.x + a.y * b.y + a.z * b.z + a.w * b.w;
}
__device__ __forceinline__ void gridBarrierF() {
    __threadfence();
    __syncthreads();
    if (threadIdx.x == 0) {
        unsigned g = *((volatile unsigned*)&g_barF_gen);
        if (atomicAdd(&g_barF_count, 1u) == gridDim.x - 1) {
            g_barF_count = 0;
            __threadfence();
            atomicExch(&g_barF_gen, g + 1);
        } else {
            while (*((volatile unsigned*)&g_barF_gen) == g) { __nanosleep(32); }
        }
    }
    __syncthreads();
    __threadfence();
}

// ================= kernel 1: GRU gate matvecs, warp per row =================
// rows 0..3071  : gi[r] = w_ih[r,:] @ x      (x = [emb ; last_context], 2048)
// rows 3072..6143: gh[r-3072] = w_hh[r-3072,:] @ h   (1024)
// 8 warps/block, 8 rows/block -> 768 blocks.
__global__ __launch_bounds__(256) void k_gate(
    const int* __restrict__ word_input,
    const float* __restrict__ last_context,
    const float* __restrict__ last_hidden,
    const float* __restrict__ embedding,
    const float* __restrict__ w_ih,
    const float* __restrict__ w_hh)
{
    __shared__ float sv[2 * HDIM];
    const int t = threadIdx.x, b = blockIdx.x;
    const int lane = t & 31, wp = t >> 5;

    if (b < 384) {
        // gi rows: stage x = [emb ; last_context]
        const int word = word_input[0];
        const float* erow = embedding + (size_t)word * HDIM;
        for (int k = t; k < HDIM; k += 256) {
            sv[k]        = erow[k];
            sv[HDIM + k] = last_context[k];
        }
        __syncthreads();
        const int r = b * 8 + wp;                       // 0..3071
        const float4* w4 = (const float4*)(w_ih + (size_t)r * (2 * HDIM));
        const float4* x4 = (const float4*)sv;
        float acc = 0.f;
#pragma unroll
        for (int i = lane; i < 512; i += 32)
            acc += dot4(__ldcs(&w4[i]), x4[i]);
        acc = warpSum(acc);
        if (lane == 0) g_gates[r] = acc;
    } else {
        // gh rows: stage h
        for (int k = t; k < HDIM; k += 256) sv[k] = last_hidden[k];
        __syncthreads();
        const int r = (b - 384) * 8 + wp;               // 0..3071
        const float4* w4 = (const float4*)(w_hh + (size_t)r * HDIM);
        const float4* h4 = (const float4*)sv;
        float acc = 0.f;
#pragma unroll
        for (int i = lane; i < 256; i += 32)
            acc += dot4(__ldcs(&w4[i]), h4[i]);
        acc = warpSum(acc);
        if (lane == 0) g_gates[3 * HDIM + r] = acc;
    }
}

// ================= kernel 2: GRU nonlinearity, single block =================
__global__ __launch_bounds__(1024) void k_act(
    const float* __restrict__ last_hidden,
    const float* __restrict__ b_ih,
    const float* __restrict__ b_hh,
    float* __restrict__ hnew_out)
{
    const int j = threadIdx.x;
    float gir = g_gates[j]            + b_ih[j];
    float giz = g_gates[j + HDIM]     + b_ih[j + HDIM];
    float gin = g_gates[j + 2 * HDIM] + b_ih[j + 2 * HDIM];
    float ghr = g_gates[j + 3 * HDIM] + b_hh[j];
    float ghz = g_gates[j + 4 * HDIM] + b_hh[j + HDIM];
    float ghn = g_gates[j + 5 * HDIM] + b_hh[j + 2 * HDIM];
    float r = 1.f / (1.f + expf(-(gir + ghr)));
    float z = 1.f / (1.f + expf(-(giz + ghz)));
    float n = tanhf(gin + r * ghn);
    float h = last_hidden[j];
    float hn = (1.f - z) * n + z * h;
    g_hnew[j] = hn;
    hnew_out[j] = hn;
}

// ================= kernel 3: attention scores, warp per row =================
__global__ __launch_bounds__(256) void k_scores(const float* __restrict__ enc)
{
    __shared__ float sh[HDIM];
    const int t = threadIdx.x, b = blockIdx.x;
    const int lane = t & 31, wp = t >> 5;
    for (int k = t; k < HDIM; k += 256) sh[k] = g_hnew[k];
    __syncthreads();
    const int s = b * 8 + wp;                           // 0..4095
    const float4* e4 = (const float4*)(enc + (size_t)s * HDIM);
    const float4* h4 = (const float4*)sh;
    float acc = 0.f;
#pragma unroll
    for (int i = lane; i < 256; i += 32)
        acc += dot4(e4[i], h4[i]);
    acc = warpSum(acc);
    if (lane == 0) g_scores[s] = acc;
}

// ================= kernel 4: softmax over S, single block =================
__global__ __launch_bounds__(1024) void k_softmax(float* __restrict__ attn_out)
{
    const int t = threadIdx.x;
    float v0 = g_scores[t];
    float v1 = g_scores[t + 1024];
    float v2 = g_scores[t + 2048];
    float v3 = g_scores[t + 3072];

    __shared__ float rb[32];
    __shared__ float bcast[2];

    float m = fmaxf(fmaxf(v0, v1), fmaxf(v2, v3));
    m = warpMax(m);
    if ((t & 31) == 0) rb[t >> 5] = m;
    __syncthreads();
    if (t < 32) {
        float x = warpMax(rb[t]);
        if (t == 0) bcast[0] = x;
    }
    __syncthreads();
    const float M = bcast[0];
    float e0 = expf(v0 - M), e1 = expf(v1 - M), e2 = expf(v2 - M), e3 = expf(v3 - M);
    float s = e0 + e1 + e2 + e3;
    s = warpSum(s);
    __syncthreads();
    if ((t & 31) == 0) rb[t >> 5] = s;
    __syncthreads();
    if (t < 32) {
        float x = warpSum(rb[t]);
        if (t == 0) bcast[1] = x;
    }
    __syncthreads();
    const float inv = 1.f / bcast[1];
    float a0 = e0 * inv, a1 = e1 * inv, a2 = e2 * inv, a3 = e3 * inv;
    g_scores[t]        = a0;  attn_out[t]        = a0;
    g_scores[t + 1024] = a1;  attn_out[t + 1024] = a1;
    g_scores[t + 2048] = a2;  attn_out[t + 2048] = a2;
    g_scores[t + 3072] = a3;  attn_out[t + 3072] = a3;
}

// ================= kernel 5: context partials (R5, proven 6.8us) =================
__global__ __launch_bounds__(256) void k_ctx_part(const float* __restrict__ enc)
{
    __shared__ float sa[CHUNK];
    const int k  = blockIdx.x * 256 + threadIdx.x;
    const int sc = blockIdx.y;
    const int s0 = sc * CHUNK;
    if (threadIdx.x < CHUNK) sa[threadIdx.x] = g_scores[s0 + threadIdx.x];
    __syncthreads();
    const float* base = enc + (size_t)s0 * HDIM + k;
    float v[CHUNK];
#pragma unroll
    for (int s = 0; s < CHUNK; s++) v[s] = base[(size_t)s * HDIM];
    float acc = 0.f;
#pragma unroll
    for (int s = 0; s < CHUNK; s++) acc += sa[s] * v[s];
    g_cpart[sc * HDIM + k] = acc;
}

// ================= kernel 6: reduce context partials =================
__global__ __launch_bounds__(256) void k_ctx_red(float* __restrict__ ctx_out)
{
    const int k = blockIdx.x * 256 + threadIdx.x;
    float acc = 0.f;
#pragma unroll
    for (int p = 0; p < NCHUNK; p++) acc += g_cpart[p * HDIM + k];
    g_context[k] = acc;
    ctx_out[k] = acc;
}

// ================= kernel 7: output projection (dominant, 412 MB) =================
__global__ __launch_bounds__(256) void k_logits(const float* __restrict__ out_w,
                                                const float* __restrict__ out_b,
                                                float* __restrict__ logits)
{
    __shared__ float sy[2 * HDIM];
    const int t = threadIdx.x;
    for (int k = t; k < HDIM; k += 256) {
        sy[k]        = g_hnew[k];
        sy[HDIM + k] = g_context[k];
    }
    __syncthreads();
    const int lane = t & 31, w = t >> 5;
    const int r = blockIdx.x * 8 + w;
    if (r >= VDIM) return;
    const float4* w4 = (const float4*)(out_w + (size_t)r * (2 * HDIM));
    const float4* y4 = (const float4*)sy;
    float acc = 0.f;
#pragma unroll
    for (int i = lane; i < 512; i += 32)
        acc += dot4(__ldcs(&w4[i]), y4[i]);
    acc = warpSum(acc);
    if (lane == 0) logits[r] = acc + out_b[r];
}

// ================= kernel 8: fused log-sum-exp + subtract (persistent) =================
__global__ __launch_bounds__(NTF, 1) void k_post(float* __restrict__ out)
{
    __shared__ float rm[32], rs[32];
    const int t = threadIdx.x, b = blockIdx.x;
    const int lane = t & 31, wp = t >> 5;
    const int gtid = b * NTF + t;
    const int stride = NBF * NTF;

    float m = -1e30f, s = 0.f;
    for (int v = gtid; v < VDIM; v += stride) {
        float x = out[v];
        float M = fmaxf(m, x);
        s = s * expf(m - M) + expf(x - M);
        m = M;
    }
#pragma unroll
    for (int o = 16; o > 0; o >>= 1) {
        float m2 = __shfl_xor_sync(0xffffffffu, m, o);
        float s2 = __shfl_xor_sync(0xffffffffu, s, o);
        float M = fmaxf(m, m2);
        s = s * expf(m - M) + s2 * expf(m2 - M);
        m = M;
    }
    if (lane == 0) { rm[wp] = m; rs[wp] = s; }
    __syncthreads();
    if (t == 0) {
        float M = rm[0], S = rs[0];
#pragma unroll
        for (int p = 1; p < 32; p++) {
            float M2 = fmaxf(M, rm[p]);
            S = S * expf(M - M2) + rs[p] * expf(rm[p] - M2);
            M = M2;
        }
        g_pair[b] = make_float2(M, S);
    }
    gridBarrierF();
    if (b == 0 && t == 0) {
        float2 p0 = g_pair[0];
        float M = p0.x, S = p0.y;
        for (int p = 1; p < NBF; p++) {
            float2 pp = g_pair[p];
            float M2 = fmaxf(M, pp.x);
            S = S * expf(M - M2) + pp.y * expf(pp.x - M2);
            M = M2;
        }
        g_lse[0] = M + logf(S);
    }
    gridBarrierF();
    const float lse = g_lse[0];
    for (int v = gtid; v < VDIM; v += stride) out[v] -= lse;
}

// ---------------- launch ----------------
extern "C" void kernel_launch(void* const* d_in, const int* in_sizes, int n_in,
                              void* d_out, int out_size)
{
    const int*   word         = (const int*)d_in[0];
    const float* last_context = (const float*)d_in[1];
    const float* last_hidden  = (const float*)d_in[2];
    const float* enc          = (const float*)d_in[3];
    const float* embedding    = (const float*)d_in[4];
    const float* w_ih         = (const float*)d_in[5];
    const float* w_hh         = (const float*)d_in[6];
    const float* b_ih         = (const float*)d_in[7];
    const float* b_hh         = (const float*)d_in[8];
    const float* out_w        = (const float*)d_in[9];
    const float* out_b        = (const float*)d_in[10];

    float* out      = (float*)d_out;
    float* o_logits = out;                    // [V]   log_softmax output
    float* o_ctx    = out + VDIM;             // [H]   context
    float* o_hnew   = out + VDIM + HDIM;      // [H]   h_new
    float* o_attn   = out + VDIM + 2 * HDIM;  // [S]   attn

    k_gate<<<768, 256>>>(word, last_context, last_hidden, embedding, w_ih, w_hh);
    k_act<<<1, 1024>>>(last_hidden, b_ih, b_hh, o_hnew);
    k_scores<<<512, 256>>>(enc);
    k_softmax<<<1, 1024>>>(o_attn);
    k_ctx_part<<<dim3(4, NCHUNK), 256>>>(enc);
    k_ctx_red<<<4, 256>>>(o_ctx);
    k_logits<<<(VDIM + 7) / 8, 256>>>(out_w, out_b, o_logits);
    k_post<<<NBF, NTF>>>(o_logits);
}